// round 14
// baseline (speedup 1.0000x reference)
#include <cuda_runtime.h>
#include <cuda_fp16.h>
#include <cstdint>

// Problem constants
#define B_  4
#define T_  2048
#define D_  1024
#define H_  16
#define HD_ 64
#define M_  (B_ * T_)        // 8192

// Scratch (device globals — no allocation allowed)
__device__ __half g_qs[B_ * H_ * T_ * HD_];   // q single fp16, pre-scaled SCL2
__device__ __half g_ks[B_ * H_ * T_ * HD_];   // k single fp16
__device__ __half g_vs[B_ * H_ * T_ * HD_];   // v single fp16
__device__ __half g_xs[M_ * D_];              // x single fp16      [M,K]
__device__ __half g_wq[D_ * 3 * D_];          // w_qkv single fp16  [K,N]
__device__ __half g_wp[D_ * D_];              // w_proj single fp16 [K,N]
__device__ __half g_as[M_ * D_];              // attention out single fp16

// ---------------------------------------------------------------------------
__device__ __forceinline__ uint32_t smem_u32(const void* p) {
    uint32_t a;
    asm("{ .reg .u64 t; cvta.to.shared.u64 t, %1; cvt.u32.u64 %0, t; }"
        : "=r"(a) : "l"(p));
    return a;
}

#define CP_ASYNC16(saddr, gaddr) \
    asm volatile("cp.async.cg.shared.global [%0], [%1], 16;" \
                 :: "r"(saddr), "l"(gaddr))
#define CP_COMMIT()  asm volatile("cp.async.commit_group;")
#define CP_WAIT1()   asm volatile("cp.async.wait_group 1;")
#define CP_WAIT0()   asm volatile("cp.async.wait_group 0;")

#define LDSM_X4(r0, r1, r2, r3, addr) \
    asm volatile("ldmatrix.sync.aligned.m8n8.x4.shared.b16 {%0,%1,%2,%3}, [%4];" \
                 : "=r"(r0), "=r"(r1), "=r"(r2), "=r"(r3) : "r"(addr))
#define LDSM_X4T(r0, r1, r2, r3, addr) \
    asm volatile("ldmatrix.sync.aligned.m8n8.x4.trans.shared.b16 {%0,%1,%2,%3}, [%4];" \
                 : "=r"(r0), "=r"(r1), "=r"(r2), "=r"(r3) : "r"(addr))

#define MMA_F16(c, a, b0, b1) \
    asm volatile("mma.sync.aligned.m16n8k16.row.col.f32.f16.f16.f32 " \
        "{%0,%1,%2,%3}, {%4,%5,%6,%7}, {%8,%9}, {%0,%1,%2,%3};" \
        : "+f"((c)[0]), "+f"((c)[1]), "+f"((c)[2]), "+f"((c)[3]) \
        : "r"((a)[0]), "r"((a)[1]), "r"((a)[2]), "r"((a)[3]), "r"(b0), "r"(b1))

// pack two fp32 -> fp16x2 (lo in low half)
__device__ __forceinline__ uint32_t pack2hf(float lo, float hi) {
    uint32_t r;
    asm("cvt.rn.f16x2.f32 %0, %1, %2;" : "=r"(r) : "f"(hi), "f"(lo));
    return r;
}
__device__ __forceinline__ float ex2(float x) {
    float r;
    asm("ex2.approx.f32 %0, %1;" : "=f"(r) : "f"(x));
    return r;
}

// ---------------------------------------------------------------------------
// Prep: single fused fp32 -> fp16 conversion over x, w_qkv, w_proj
// ---------------------------------------------------------------------------
#define XN   (M_ * D_)           // 8388608
#define WQN  (D_ * 3 * D_)       // 3145728
#define WPN  (D_ * D_)           // 1048576
#define CONVN (XN + WQN + WPN)

__global__ void conv_all(const float* __restrict__ x,
                         const float* __restrict__ wq,
                         const float* __restrict__ wp)
{
    long i = ((long)blockIdx.x * 256 + threadIdx.x) * 4;
    const float* src;
    __half* dst;
    long j;
    if (i < XN)            { src = x;  dst = g_xs; j = i; }
    else if (i < XN + WQN) { src = wq; dst = g_wq; j = i - XN; }
    else                   { src = wp; dst = g_wp; j = i - XN - WQN; }
    float4 v = *(const float4*)(src + j);
    *(uint2*)(dst + j) = make_uint2(pack2hf(v.x, v.y), pack2hf(v.z, v.w));
}

// ---------------------------------------------------------------------------
// fp16 GEMM via mma.sync, BK=64 chunks (R13, proven).
// 8 warps, 64x32 warp tiles (16 warps/SM), 3-stage cp.async, 1 sync/chunk.
// EPI=0: fp32 store + bias.  EPI=1: QKV scatter (q pre-scaled, k, v single).
// ---------------------------------------------------------------------------
#define GEMM_SMEM (3 * 32768)
#define SCL2 0.1803368801111204f   // 0.125 * log2(e)

template <int EPI>
__global__ __launch_bounds__(256, 2) void gemm_f16(
    const __half* __restrict__ A, const __half* __restrict__ Bmat,
    const float* __restrict__ bias, float* __restrict__ C, int N)
{
    extern __shared__ char sm[];
    const uint32_t sb = smem_u32(sm);
    const int tid = threadIdx.x;
    const int warp = tid >> 5, lane = tid & 31;
    const int m0 = blockIdx.y * 128, n0 = blockIdx.x * 128;
    const int K = 1024;

    const int a_row = tid >> 1, a_u0 = (tid & 1) * 4;
    const int b_row = tid >> 2, b_u0 = (tid & 3) * 4;

    auto load_stage = [&](int c, int buf) {
        const uint32_t st = sb + buf * 32768;
        const __half* ag = A + (long)(m0 + a_row) * K + c * 64;
        const __half* bg = Bmat + (long)(c * 64 + b_row) * N + n0;
        #pragma unroll
        for (int i = 0; i < 4; i++) {
            const int au = a_u0 + i, bu = b_u0 + i;
            CP_ASYNC16(st + a_row * 128 + ((au ^ (a_row & 7)) << 4), ag + au * 8);
            CP_ASYNC16(st + 16384 + b_row * 256 + ((bu ^ (b_row & 7)) << 4),
                       bg + bu * 8);
        }
        CP_COMMIT();
    };

    const int wm = (warp & 1) * 64;
    const int wn = (warp >> 1) * 32;

    float acc[4][4][4] = {};

    const int a_lr = lane & 15;
    const int a_lk = lane >> 4;
    const int b_lk = lane & 15;
    const int b_ln = lane >> 4;
    const int nu0 = wn >> 3;

    load_stage(0, 0);
    load_stage(1, 1);

    int buf = 0;                 // c % 3
    for (int c = 0; c < 16; c++) {
        if (c < 15) CP_WAIT1(); else CP_WAIT0();
        __syncthreads();
        if (c + 2 < 16) {
            int nb = buf + 2; if (nb >= 3) nb -= 3;
            load_stage(c + 2, nb);
        }

        const uint32_t st = sb + buf * 32768;
        #pragma unroll
        for (int ks = 0; ks < 4; ks++) {
            uint32_t ah[4][4];
            #pragma unroll
            for (int mi = 0; mi < 4; mi++) {
                const int row = wm + mi * 16 + a_lr;
                const int ku = ks * 2 + a_lk;
                const uint32_t off = row * 128 + ((ku ^ (row & 7)) << 4);
                LDSM_X4(ah[mi][0], ah[mi][1], ah[mi][2], ah[mi][3], st + off);
            }
            #pragma unroll
            for (int bi = 0; bi < 2; bi++) {
                const int krow = ks * 16 + b_lk;
                const int nu = nu0 + bi * 2 + b_ln;
                const uint32_t boff = 16384 + krow * 256 + ((nu ^ (krow & 7)) << 4);
                uint32_t bh[4];
                LDSM_X4T(bh[0], bh[1], bh[2], bh[3], st + boff);
                #pragma unroll
                for (int mi = 0; mi < 4; mi++) {
                    MMA_F16(acc[mi][bi * 2],     ah[mi], bh[0], bh[1]);
                    MMA_F16(acc[mi][bi * 2 + 1], ah[mi], bh[2], bh[3]);
                }
            }
        }
        if (++buf == 3) buf = 0;
    }

    // Epilogue
    const int tg = lane >> 2, ti = lane & 3;
    #pragma unroll
    for (int mi = 0; mi < 4; mi++) {
        #pragma unroll
        for (int nj = 0; nj < 4; nj++) {
            const int n = n0 + wn + nj * 8 + ti * 2;
            const float bx = __ldg(&bias[n]), by = __ldg(&bias[n + 1]);
            #pragma unroll
            for (int half = 0; half < 2; half++) {
                const int m = m0 + wm + mi * 16 + tg + half * 8;
                float ox = acc[mi][nj][half * 2 + 0] + bx;
                float oy = acc[mi][nj][half * 2 + 1] + by;
                if (EPI == 0) {
                    *(float2*)(C + (long)m * N + n) = make_float2(ox, oy);
                } else {
                    const int bidx = m >> 11, t = m & (T_ - 1);
                    const int which = n >> 10;
                    const int rem = n & 1023;
                    const int h = rem >> 6, hd = rem & 63;
                    long off = (((long)bidx * H_ + h) * T_ + t) * HD_ + hd;
                    if (which == 0) {
                        *(uint32_t*)(g_qs + off) = pack2hf(ox * SCL2, oy * SCL2);
                    } else if (which == 1) {
                        *(uint32_t*)(g_ks + off) = pack2hf(ox, oy);
                    } else {
                        *(uint32_t*)(g_vs + off) = pack2hf(ox, oy);
                    }
                }
            }
        }
    }
}

// ---------------------------------------------------------------------------
// Tensor-core causal flash attention, kv tiles of 128 (halves softmax passes
// and barriers vs kv64; R13 profile showed softmax/barrier overhead
// interleaving ~150 scalar ops per 64 mma).
// Q fragments reloaded from smem per chunk to keep peak regs < 128
// (sacc is 64 regs at kv128) -> 2 CTAs/SM preserved.
// smem: Q 16KB + 2 stages x (K 16KB + V 16KB) = 80KB/CTA; 2 x 80 = 160KB.
// ---------------------------------------------------------------------------
#define ATTN_SMEM (16384 + 2 * 32768)

__global__ __launch_bounds__(256, 2) void attn_tc_kernel()
{
    extern __shared__ char sm[];
    const uint32_t sb = smem_u32(sm);
    const int tid = threadIdx.x;
    const int w = tid >> 5, lane = tid & 31;
    const int tg = lane >> 2, ti = lane & 3;
    const int qt = 15 - blockIdx.x;           // big tiles first
    const int bh = blockIdx.y;
    const int qbase = qt * 128 + w * 16;
    const int r0 = qbase + tg;                // thread rows r0, r0+8

    const long bhoff = (long)bh * T_ * HD_;

    // ---- issue Q loads (rows of 128B, swizzled) + KV tile 0
    {
        const int row = tid >> 1;
        const int u0 = (tid & 1) * 4;
        const long gq = bhoff + (long)(qt * 128 + row) * HD_;
        #pragma unroll
        for (int i = 0; i < 4; i++) {
            const int u = u0 + i;
            CP_ASYNC16(sb + row * 128 + ((u ^ (row & 7)) << 4), g_qs + gq + u * 8);
        }
    }
    // KV producer: 256 threads = 2 parts (K, V) x 128 rows, 8 units each
    const int kvp  = tid >> 7;           // 0 = K, 1 = V
    const int kvr  = tid & 127;          // row 0..127
    const __half* kvsrc = kvp ? g_vs : g_ks;
    const uint32_t kvdst_off = kvp * 16384 + kvr * 128;

    auto load_kv = [&](int kb, int buf) {
        const uint32_t st = sb + 16384 + buf * 32768;
        const long gs = bhoff + (long)(kb * 128 + kvr) * HD_;
        #pragma unroll
        for (int u = 0; u < 8; u++)
            CP_ASYNC16(st + kvdst_off + ((u ^ (kvr & 7)) << 4), kvsrc + gs + u * 8);
    };
    load_kv(0, 0);
    CP_COMMIT();
    CP_WAIT0();
    __syncthreads();

    // Q fragment smem addresses (fragments reloaded per chunk — reg pressure)
    uint32_t qad[4];
    #pragma unroll
    for (int s = 0; s < 4; s++) {
        const int row = w * 16 + (lane & 15);
        const int ku = s * 2 + (lane >> 4);
        qad[s] = sb + row * 128 + ((ku ^ (row & 7)) << 4);
    }

    float oacc[8][4] = {};
    float m2a = -1e30f, m2b = -1e30f;
    float la = 0.f, lb = 0.f;

    const int nt = qt + 1;
    for (int kb = 0; kb < nt; kb++) {
        if (kb > 0) CP_WAIT0();
        __syncthreads();
        if (kb + 1 < nt) { load_kv(kb + 1, (kb + 1) & 1); CP_COMMIT(); }

        const uint32_t stK = sb + 16384 + (kb & 1) * 32768;
        const uint32_t stV = stK + 16384;

        // ---- S = q K   (log2 domain already; both single fp16)
        float sacc[16][4] = {};
        #pragma unroll
        for (int s = 0; s < 4; s++) {
            uint32_t qa[4];
            LDSM_X4(qa[0], qa[1], qa[2], qa[3], qad[s]);
            #pragma unroll
            for (int g = 0; g < 8; g++) {
                const int row = g * 16 + (lane & 15);
                const uint32_t ka = stK + row * 128 +
                    (((s * 2 + (lane >> 4)) ^ (row & 7)) << 4);
                uint32_t h0, h1, h2, h3;
                LDSM_X4(h0, h1, h2, h3, ka);
                MMA_F16(sacc[2 * g],     qa, h0, h2);
                MMA_F16(sacc[2 * g + 1], qa, h1, h3);
            }
        }

        // ---- causal mask + row max
        const bool needmask = (kb * 128 + 127) > r0;
        float mra = -1e30f, mrb = -1e30f;
        #pragma unroll
        for (int j = 0; j < 16; j++) {
            const int c0 = kb * 128 + 8 * j + 2 * ti, c1 = c0 + 1;
            float z0 = sacc[j][0];
            float z1 = sacc[j][1];
            float z2 = sacc[j][2];
            float z3 = sacc[j][3];
            if (needmask) {
                if (c0 > r0) z0 = -1e30f;
                if (c1 > r0) z1 = -1e30f;
                if (c0 > r0 + 8) z2 = -1e30f;
                if (c1 > r0 + 8) z3 = -1e30f;
            }
            sacc[j][0] = z0; sacc[j][1] = z1; sacc[j][2] = z2; sacc[j][3] = z3;
            mra = fmaxf(mra, fmaxf(z0, z1));
            mrb = fmaxf(mrb, fmaxf(z2, z3));
        }
        mra = fmaxf(mra, __shfl_xor_sync(0xffffffffu, mra, 1));
        mra = fmaxf(mra, __shfl_xor_sync(0xffffffffu, mra, 2));
        mrb = fmaxf(mrb, __shfl_xor_sync(0xffffffffu, mrb, 1));
        mrb = fmaxf(mrb, __shfl_xor_sync(0xffffffffu, mrb, 2));

        const float mna = fmaxf(m2a, mra);
        const float mnb = fmaxf(m2b, mrb);
        const float alpa = ex2(m2a - mna);
        const float alpb = ex2(m2b - mnb);
        m2a = mna; m2b = mnb;

        #pragma unroll
        for (int j = 0; j < 8; j++) {
            oacc[j][0] *= alpa; oacc[j][1] *= alpa;
            oacc[j][2] *= alpb; oacc[j][3] *= alpb;
        }

        // ---- exp + pack P to single fp16 (A-frag layout; overwrites sacc
        //      liveness progressively)
        uint32_t pha[16], phb[16];
        float sa = 0.f, sbm = 0.f;
        #pragma unroll
        for (int j = 0; j < 16; j++) {
            float p0 = ex2(sacc[j][0] - m2a);
            float p1 = ex2(sacc[j][1] - m2a);
            float p2 = ex2(sacc[j][2] - m2b);
            float p3 = ex2(sacc[j][3] - m2b);
            sa += p0 + p1; sbm += p2 + p3;
            pha[j] = pack2hf(p0, p1);
            phb[j] = pack2hf(p2, p3);
        }
        sa  += __shfl_xor_sync(0xffffffffu, sa, 1);
        sa  += __shfl_xor_sync(0xffffffffu, sa, 2);
        sbm += __shfl_xor_sync(0xffffffffu, sbm, 1);
        sbm += __shfl_xor_sync(0xffffffffu, sbm, 2);
        la = la * alpa + sa;
        lb = lb * alpb + sbm;

        // ---- O += P V
        #pragma unroll
        for (int s = 0; s < 8; s++) {
            uint32_t aH[4] = {pha[2 * s], phb[2 * s], pha[2 * s + 1], phb[2 * s + 1]};
            #pragma unroll
            for (int b = 0; b < 4; b++) {
                const int krow = s * 16 + (lane & 15);
                const uint32_t va = stV + krow * 128 +
                    (((b * 2 + (lane >> 4)) ^ (krow & 7)) << 4);
                uint32_t h0, h1, h2, h3;
                LDSM_X4T(h0, h1, h2, h3, va);
                MMA_F16(oacc[2 * b],     aH, h0, h1);
                MMA_F16(oacc[2 * b + 1], aH, h2, h3);
            }
        }
    }

    // ---- epilogue: normalize, single fp16, write [B,T,H*HD]
    const float inva = 1.0f / la, invb = 1.0f / lb;
    const int bidx = bh >> 4, h = bh & 15;
    const long rowa = ((long)(bidx * T_ + qbase + tg)) * D_ + h * HD_;
    const long rowb = rowa + 8L * D_;
    #pragma unroll
    for (int j = 0; j < 8; j++) {
        const int col = 8 * j + 2 * ti;
        *(uint32_t*)(g_as + rowa + col) = pack2hf(oacc[j][0] * inva, oacc[j][1] * inva);
        *(uint32_t*)(g_as + rowb + col) = pack2hf(oacc[j][2] * invb, oacc[j][3] * invb);
    }
}

// ---------------------------------------------------------------------------
extern "C" void kernel_launch(void* const* d_in, const int* in_sizes, int n_in,
                              void* d_out, int out_size)
{
    const float* x      = (const float*)d_in[0];
    const float* w_qkv  = (const float*)d_in[1];
    const float* b_qkv  = (const float*)d_in[2];
    const float* w_proj = (const float*)d_in[3];
    const float* b_proj = (const float*)d_in[4];
    float* out = (float*)d_out;

    __half *xs, *wq, *wp, *as;
    cudaGetSymbolAddress((void**)&xs, g_xs);
    cudaGetSymbolAddress((void**)&wq, g_wq);
    cudaGetSymbolAddress((void**)&wp, g_wp);
    cudaGetSymbolAddress((void**)&as, g_as);

    // 0) fused conversions to fp16 (one launch)
    conv_all<<<CONVN / 1024, 256>>>(x, w_qkv, w_proj);

    // 1) QKV GEMM (fp16, BK=64) -> q (scaled) / k / v single fp16
    cudaFuncSetAttribute((const void*)gemm_f16<1>,
                         cudaFuncAttributeMaxDynamicSharedMemorySize, GEMM_SMEM);
    gemm_f16<1><<<dim3(3 * D_ / 128, M_ / 128), 256, GEMM_SMEM>>>(
        xs, wq, b_qkv, nullptr, 3 * D_);

    // 2) tensor-core flash attention (kv128, 2 CTAs/SM)
    cudaFuncSetAttribute((const void*)attn_tc_kernel,
                         cudaFuncAttributeMaxDynamicSharedMemorySize, ATTN_SMEM);
    attn_tc_kernel<<<dim3(T_ / 128, B_ * H_), 256, ATTN_SMEM>>>();

    // 3) proj GEMM (fp16, BK=64)
    cudaFuncSetAttribute((const void*)gemm_f16<0>,
                         cudaFuncAttributeMaxDynamicSharedMemorySize, GEMM_SMEM);
    gemm_f16<0><<<dim3(D_ / 128, M_ / 128), 256, GEMM_SMEM>>>(
        as, wp, b_proj, out, D_);
}

// round 15
// speedup vs baseline: 1.0980x; 1.0980x over previous
#include <cuda_runtime.h>
#include <cuda_fp16.h>
#include <cstdint>

// Problem constants
#define B_  4
#define T_  2048
#define D_  1024
#define H_  16
#define HD_ 64
#define M_  (B_ * T_)        // 8192

// Scratch (device globals — no allocation allowed)
__device__ __half g_qs[B_ * H_ * T_ * HD_];   // q single fp16, pre-scaled SCL2
__device__ __half g_ks[B_ * H_ * T_ * HD_];   // k single fp16
__device__ __half g_vs[B_ * H_ * T_ * HD_];   // v single fp16
__device__ __half g_xs[M_ * D_];              // x single fp16      [M,K]
__device__ __half g_wq[D_ * 3 * D_];          // w_qkv single fp16  [K,N]
__device__ __half g_wp[D_ * D_];              // w_proj single fp16 [K,N]
__device__ __half g_as[M_ * D_];              // attention out single fp16

// ---------------------------------------------------------------------------
__device__ __forceinline__ uint32_t smem_u32(const void* p) {
    uint32_t a;
    asm("{ .reg .u64 t; cvta.to.shared.u64 t, %1; cvt.u32.u64 %0, t; }"
        : "=r"(a) : "l"(p));
    return a;
}

#define CP_ASYNC16(saddr, gaddr) \
    asm volatile("cp.async.cg.shared.global [%0], [%1], 16;" \
                 :: "r"(saddr), "l"(gaddr))
#define CP_COMMIT()  asm volatile("cp.async.commit_group;")
#define CP_WAIT1()   asm volatile("cp.async.wait_group 1;")
#define CP_WAIT0()   asm volatile("cp.async.wait_group 0;")

#define LDSM_X4(r0, r1, r2, r3, addr) \
    asm volatile("ldmatrix.sync.aligned.m8n8.x4.shared.b16 {%0,%1,%2,%3}, [%4];" \
                 : "=r"(r0), "=r"(r1), "=r"(r2), "=r"(r3) : "r"(addr))
#define LDSM_X4T(r0, r1, r2, r3, addr) \
    asm volatile("ldmatrix.sync.aligned.m8n8.x4.trans.shared.b16 {%0,%1,%2,%3}, [%4];" \
                 : "=r"(r0), "=r"(r1), "=r"(r2), "=r"(r3) : "r"(addr))

#define MMA_F16(c, a, b0, b1) \
    asm volatile("mma.sync.aligned.m16n8k16.row.col.f32.f16.f16.f32 " \
        "{%0,%1,%2,%3}, {%4,%5,%6,%7}, {%8,%9}, {%0,%1,%2,%3};" \
        : "+f"((c)[0]), "+f"((c)[1]), "+f"((c)[2]), "+f"((c)[3]) \
        : "r"((a)[0]), "r"((a)[1]), "r"((a)[2]), "r"((a)[3]), "r"(b0), "r"(b1))

// pack two fp32 -> fp16x2 (lo in low half)
__device__ __forceinline__ uint32_t pack2hf(float lo, float hi) {
    uint32_t r;
    asm("cvt.rn.f16x2.f32 %0, %1, %2;" : "=r"(r) : "f"(hi), "f"(lo));
    return r;
}
__device__ __forceinline__ float ex2(float x) {
    float r;
    asm("ex2.approx.f32 %0, %1;" : "=f"(r) : "f"(x));
    return r;
}

// ---------------------------------------------------------------------------
// Prep: single fused fp32 -> fp16 conversion over x, w_qkv, w_proj
// (R14's one validated improvement: 3 launches -> 1)
// ---------------------------------------------------------------------------
#define XN   (M_ * D_)           // 8388608
#define WQN  (D_ * 3 * D_)       // 3145728
#define WPN  (D_ * D_)           // 1048576
#define CONVN (XN + WQN + WPN)

__global__ void conv_all(const float* __restrict__ x,
                         const float* __restrict__ wq,
                         const float* __restrict__ wp)
{
    long i = ((long)blockIdx.x * 256 + threadIdx.x) * 4;
    const float* src;
    __half* dst;
    long j;
    if (i < XN)            { src = x;  dst = g_xs; j = i; }
    else if (i < XN + WQN) { src = wq; dst = g_wq; j = i - XN; }
    else                   { src = wp; dst = g_wp; j = i - XN - WQN; }
    float4 v = *(const float4*)(src + j);
    *(uint2*)(dst + j) = make_uint2(pack2hf(v.x, v.y), pack2hf(v.z, v.w));
}

// ---------------------------------------------------------------------------
// fp16 GEMM via mma.sync, BK=64 chunks (R13, proven).
// 8 warps, 64x32 warp tiles (16 warps/SM), 3-stage cp.async, 1 sync/chunk.
// EPI=0: fp32 store + bias.  EPI=1: QKV scatter (q pre-scaled, k, v single).
// ---------------------------------------------------------------------------
#define GEMM_SMEM (3 * 32768)
#define SCL2 0.1803368801111204f   // 0.125 * log2(e)

template <int EPI>
__global__ __launch_bounds__(256, 2) void gemm_f16(
    const __half* __restrict__ A, const __half* __restrict__ Bmat,
    const float* __restrict__ bias, float* __restrict__ C, int N)
{
    extern __shared__ char sm[];
    const uint32_t sb = smem_u32(sm);
    const int tid = threadIdx.x;
    const int warp = tid >> 5, lane = tid & 31;
    const int m0 = blockIdx.y * 128, n0 = blockIdx.x * 128;
    const int K = 1024;

    const int a_row = tid >> 1, a_u0 = (tid & 1) * 4;
    const int b_row = tid >> 2, b_u0 = (tid & 3) * 4;

    auto load_stage = [&](int c, int buf) {
        const uint32_t st = sb + buf * 32768;
        const __half* ag = A + (long)(m0 + a_row) * K + c * 64;
        const __half* bg = Bmat + (long)(c * 64 + b_row) * N + n0;
        #pragma unroll
        for (int i = 0; i < 4; i++) {
            const int au = a_u0 + i, bu = b_u0 + i;
            CP_ASYNC16(st + a_row * 128 + ((au ^ (a_row & 7)) << 4), ag + au * 8);
            CP_ASYNC16(st + 16384 + b_row * 256 + ((bu ^ (b_row & 7)) << 4),
                       bg + bu * 8);
        }
        CP_COMMIT();
    };

    const int wm = (warp & 1) * 64;
    const int wn = (warp >> 1) * 32;

    float acc[4][4][4] = {};

    const int a_lr = lane & 15;
    const int a_lk = lane >> 4;
    const int b_lk = lane & 15;
    const int b_ln = lane >> 4;
    const int nu0 = wn >> 3;

    load_stage(0, 0);
    load_stage(1, 1);

    int buf = 0;                 // c % 3
    for (int c = 0; c < 16; c++) {
        if (c < 15) CP_WAIT1(); else CP_WAIT0();
        __syncthreads();
        if (c + 2 < 16) {
            int nb = buf + 2; if (nb >= 3) nb -= 3;
            load_stage(c + 2, nb);
        }

        const uint32_t st = sb + buf * 32768;
        #pragma unroll
        for (int ks = 0; ks < 4; ks++) {
            uint32_t ah[4][4];
            #pragma unroll
            for (int mi = 0; mi < 4; mi++) {
                const int row = wm + mi * 16 + a_lr;
                const int ku = ks * 2 + a_lk;
                const uint32_t off = row * 128 + ((ku ^ (row & 7)) << 4);
                LDSM_X4(ah[mi][0], ah[mi][1], ah[mi][2], ah[mi][3], st + off);
            }
            #pragma unroll
            for (int bi = 0; bi < 2; bi++) {
                const int krow = ks * 16 + b_lk;
                const int nu = nu0 + bi * 2 + b_ln;
                const uint32_t boff = 16384 + krow * 256 + ((nu ^ (krow & 7)) << 4);
                uint32_t bh[4];
                LDSM_X4T(bh[0], bh[1], bh[2], bh[3], st + boff);
                #pragma unroll
                for (int mi = 0; mi < 4; mi++) {
                    MMA_F16(acc[mi][bi * 2],     ah[mi], bh[0], bh[1]);
                    MMA_F16(acc[mi][bi * 2 + 1], ah[mi], bh[2], bh[3]);
                }
            }
        }
        if (++buf == 3) buf = 0;
    }

    // Epilogue
    const int tg = lane >> 2, ti = lane & 3;
    #pragma unroll
    for (int mi = 0; mi < 4; mi++) {
        #pragma unroll
        for (int nj = 0; nj < 4; nj++) {
            const int n = n0 + wn + nj * 8 + ti * 2;
            const float bx = __ldg(&bias[n]), by = __ldg(&bias[n + 1]);
            #pragma unroll
            for (int half = 0; half < 2; half++) {
                const int m = m0 + wm + mi * 16 + tg + half * 8;
                float ox = acc[mi][nj][half * 2 + 0] + bx;
                float oy = acc[mi][nj][half * 2 + 1] + by;
                if (EPI == 0) {
                    *(float2*)(C + (long)m * N + n) = make_float2(ox, oy);
                } else {
                    const int bidx = m >> 11, t = m & (T_ - 1);
                    const int which = n >> 10;
                    const int rem = n & 1023;
                    const int h = rem >> 6, hd = rem & 63;
                    long off = (((long)bidx * H_ + h) * T_ + t) * HD_ + hd;
                    if (which == 0) {
                        *(uint32_t*)(g_qs + off) = pack2hf(ox * SCL2, oy * SCL2);
                    } else if (which == 1) {
                        *(uint32_t*)(g_ks + off) = pack2hf(ox, oy);
                    } else {
                        *(uint32_t*)(g_vs + off) = pack2hf(ox, oy);
                    }
                }
            }
        }
    }
}

// ---------------------------------------------------------------------------
// Tensor-core causal flash attention — R13 kv64 configuration (proven 145us;
// R14's kv128 spilled: sacc 64 + pha/phb 32 + oacc 32 > 128-reg cap).
// S = q K (32 mma/chunk); PV = P V (32 mma/chunk); all single fp16.
// smem: Q 16KB + 2 stages x (K 8KB + V 8KB) = 48KB/CTA; 2 CTAs/SM.
// ---------------------------------------------------------------------------
#define ATTN_SMEM (16384 + 2 * 16384)

__global__ __launch_bounds__(256, 2) void attn_tc_kernel()
{
    extern __shared__ char sm[];
    const uint32_t sb = smem_u32(sm);
    const int tid = threadIdx.x;
    const int w = tid >> 5, lane = tid & 31;
    const int tg = lane >> 2, ti = lane & 3;
    const int qt = 15 - blockIdx.x;           // big tiles first
    const int bh = blockIdx.y;
    const int qbase = qt * 128 + w * 16;
    const int r0 = qbase + tg;                // thread rows r0, r0+8

    const long bhoff = (long)bh * T_ * HD_;

    // ---- issue Q loads (rows of 128B, swizzled) + KV tile 0
    {
        const int row = tid >> 1;
        const int u0 = (tid & 1) * 4;
        const long gq = bhoff + (long)(qt * 128 + row) * HD_;
        #pragma unroll
        for (int i = 0; i < 4; i++) {
            const int u = u0 + i;
            CP_ASYNC16(sb + row * 128 + ((u ^ (row & 7)) << 4), g_qs + gq + u * 8);
        }
    }
    // KV producer: 256 threads = 2 parts (K, V) x 64 rows x 2 half-rows
    const int kvp  = tid >> 7;           // 0 = K, 1 = V
    const int kvr  = (tid & 127) >> 1;   // row 0..63
    const int kvh  = tid & 1;            // half-row: 4 x 16B units
    const __half* kvsrc = kvp ? g_vs : g_ks;
    const uint32_t kvdst_off = kvp * 8192 + kvr * 128;

    auto load_kv = [&](int kb, int buf) {
        const uint32_t st = sb + 16384 + buf * 16384;
        const long gs = bhoff + (long)(kb * 64 + kvr) * HD_ + kvh * 32;
        #pragma unroll
        for (int u = 0; u < 4; u++) {
            const int uu = kvh * 4 + u;
            CP_ASYNC16(st + kvdst_off + ((uu ^ (kvr & 7)) << 4), kvsrc + gs + u * 8);
        }
    };
    load_kv(0, 0);
    CP_COMMIT();
    CP_WAIT0();
    __syncthreads();

    // ---- Q fragments (single fp16, pre-scaled)
    uint32_t qh[4][4];
    #pragma unroll
    for (int s = 0; s < 4; s++) {
        const int row = w * 16 + (lane & 15);
        const int ku = s * 2 + (lane >> 4);
        const uint32_t ad = sb + row * 128 + ((ku ^ (row & 7)) << 4);
        LDSM_X4(qh[s][0], qh[s][1], qh[s][2], qh[s][3], ad);
    }

    float oacc[8][4] = {};
    float m2a = -1e30f, m2b = -1e30f;
    float la = 0.f, lb = 0.f;

    const int nt = 2 * qt + 2;
    for (int kb = 0; kb < nt; kb++) {
        if (kb > 0) CP_WAIT0();
        __syncthreads();
        if (kb + 1 < nt) { load_kv(kb + 1, (kb + 1) & 1); CP_COMMIT(); }

        if (kb * 64 > qbase + 15) continue;   // warp fully masked

        const uint32_t stK = sb + 16384 + (kb & 1) * 16384;
        const uint32_t stV = stK + 8192;

        // ---- S = q K   (log2 domain already; both single fp16)
        float sacc[8][4] = {};
        #pragma unroll
        for (int s = 0; s < 4; s++) {
            #pragma unroll
            for (int g = 0; g < 4; g++) {
                const int row = g * 16 + (lane & 15);
                const uint32_t ka = stK + row * 128 +
                    (((s * 2 + (lane >> 4)) ^ (row & 7)) << 4);
                uint32_t h0, h1, h2, h3;
                LDSM_X4(h0, h1, h2, h3, ka);
                MMA_F16(sacc[2 * g],     qh[s], h0, h2);
                MMA_F16(sacc[2 * g + 1], qh[s], h1, h3);
            }
        }

        // ---- causal mask + row max
        const bool needmask = (kb * 64 + 63) > r0;
        float mra = -1e30f, mrb = -1e30f;
        #pragma unroll
        for (int j = 0; j < 8; j++) {
            const int c0 = kb * 64 + 8 * j + 2 * ti, c1 = c0 + 1;
            float z0 = sacc[j][0];
            float z1 = sacc[j][1];
            float z2 = sacc[j][2];
            float z3 = sacc[j][3];
            if (needmask) {
                if (c0 > r0) z0 = -1e30f;
                if (c1 > r0) z1 = -1e30f;
                if (c0 > r0 + 8) z2 = -1e30f;
                if (c1 > r0 + 8) z3 = -1e30f;
            }
            sacc[j][0] = z0; sacc[j][1] = z1; sacc[j][2] = z2; sacc[j][3] = z3;
            mra = fmaxf(mra, fmaxf(z0, z1));
            mrb = fmaxf(mrb, fmaxf(z2, z3));
        }
        mra = fmaxf(mra, __shfl_xor_sync(0xffffffffu, mra, 1));
        mra = fmaxf(mra, __shfl_xor_sync(0xffffffffu, mra, 2));
        mrb = fmaxf(mrb, __shfl_xor_sync(0xffffffffu, mrb, 1));
        mrb = fmaxf(mrb, __shfl_xor_sync(0xffffffffu, mrb, 2));

        const float mna = fmaxf(m2a, mra);
        const float mnb = fmaxf(m2b, mrb);
        const float alpa = ex2(m2a - mna);
        const float alpb = ex2(m2b - mnb);
        m2a = mna; m2b = mnb;

        #pragma unroll
        for (int j = 0; j < 8; j++) {
            oacc[j][0] *= alpa; oacc[j][1] *= alpa;
            oacc[j][2] *= alpb; oacc[j][3] *= alpb;
        }

        // ---- exp + pack P to single fp16 (A-frag layout)
        uint32_t pha[8], phb[8];
        float sa = 0.f, sbm = 0.f;
        #pragma unroll
        for (int j = 0; j < 8; j++) {
            float p0 = ex2(sacc[j][0] - m2a);
            float p1 = ex2(sacc[j][1] - m2a);
            float p2 = ex2(sacc[j][2] - m2b);
            float p3 = ex2(sacc[j][3] - m2b);
            sa += p0 + p1; sbm += p2 + p3;
            pha[j] = pack2hf(p0, p1);
            phb[j] = pack2hf(p2, p3);
        }
        sa  += __shfl_xor_sync(0xffffffffu, sa, 1);
        sa  += __shfl_xor_sync(0xffffffffu, sa, 2);
        sbm += __shfl_xor_sync(0xffffffffu, sbm, 1);
        sbm += __shfl_xor_sync(0xffffffffu, sbm, 2);
        la = la * alpa + sa;
        lb = lb * alpb + sbm;

        // ---- O += P V
        #pragma unroll
        for (int s = 0; s < 4; s++) {
            uint32_t aH[4] = {pha[2 * s], phb[2 * s], pha[2 * s + 1], phb[2 * s + 1]};
            #pragma unroll
            for (int b = 0; b < 4; b++) {
                const int krow = s * 16 + (lane & 15);
                const uint32_t va = stV + krow * 128 +
                    (((b * 2 + (lane >> 4)) ^ (krow & 7)) << 4);
                uint32_t h0, h1, h2, h3;
                LDSM_X4T(h0, h1, h2, h3, va);
                MMA_F16(oacc[2 * b],     aH, h0, h1);
                MMA_F16(oacc[2 * b + 1], aH, h2, h3);
            }
        }
    }

    // ---- epilogue: normalize, single fp16, write [B,T,H*HD]
    const float inva = 1.0f / la, invb = 1.0f / lb;
    const int bidx = bh >> 4, h = bh & 15;
    const long rowa = ((long)(bidx * T_ + qbase + tg)) * D_ + h * HD_;
    const long rowb = rowa + 8L * D_;
    #pragma unroll
    for (int j = 0; j < 8; j++) {
        const int col = 8 * j + 2 * ti;
        *(uint32_t*)(g_as + rowa + col) = pack2hf(oacc[j][0] * inva, oacc[j][1] * inva);
        *(uint32_t*)(g_as + rowb + col) = pack2hf(oacc[j][2] * invb, oacc[j][3] * invb);
    }
}

// ---------------------------------------------------------------------------
extern "C" void kernel_launch(void* const* d_in, const int* in_sizes, int n_in,
                              void* d_out, int out_size)
{
    const float* x      = (const float*)d_in[0];
    const float* w_qkv  = (const float*)d_in[1];
    const float* b_qkv  = (const float*)d_in[2];
    const float* w_proj = (const float*)d_in[3];
    const float* b_proj = (const float*)d_in[4];
    float* out = (float*)d_out;

    __half *xs, *wq, *wp, *as;
    cudaGetSymbolAddress((void**)&xs, g_xs);
    cudaGetSymbolAddress((void**)&wq, g_wq);
    cudaGetSymbolAddress((void**)&wp, g_wp);
    cudaGetSymbolAddress((void**)&as, g_as);

    // 0) fused conversions to fp16 (one launch)
    conv_all<<<CONVN / 1024, 256>>>(x, w_qkv, w_proj);

    // 1) QKV GEMM (fp16, BK=64) -> q (scaled) / k / v single fp16
    cudaFuncSetAttribute((const void*)gemm_f16<1>,
                         cudaFuncAttributeMaxDynamicSharedMemorySize, GEMM_SMEM);
    gemm_f16<1><<<dim3(3 * D_ / 128, M_ / 128), 256, GEMM_SMEM>>>(
        xs, wq, b_qkv, nullptr, 3 * D_);

    // 2) tensor-core flash attention (kv64, 2 CTAs/SM — R13 proven)
    cudaFuncSetAttribute((const void*)attn_tc_kernel,
                         cudaFuncAttributeMaxDynamicSharedMemorySize, ATTN_SMEM);
    attn_tc_kernel<<<dim3(T_ / 128, B_ * H_), 256, ATTN_SMEM>>>();

    // 3) proj GEMM (fp16, BK=64)
    cudaFuncSetAttribute((const void*)gemm_f16<0>,
                         cudaFuncAttributeMaxDynamicSharedMemorySize, GEMM_SMEM);
    gemm_f16<0><<<dim3(D_ / 128, M_ / 128), 256, GEMM_SMEM>>>(
        as, wp, b_proj, out, D_);
}